// round 11
// baseline (speedup 1.0000x reference)
#include <cuda_runtime.h>
#include <math.h>

#define PS      16
#define EMB     64
#define TP      128           // patches per block
#define WSTR    68            // wT row stride (floats)
#define SSTR    132           // sT row stride (floats), 16B-aligned blocks
#define NPATCH  98304
#define PPB     3072          // patches per batch image
#define NBLK    (NPATCH / TP) // 768

// dynamic shared layout (floats):
//   wT   [256][WSTR]  : 69632 B
//   sT   [256][SSTR]  : 135168 B   (sT[k][p], p in [0,128))
//   masks[128][8] u32 : 4096 B
//   bs   [64]         : 256 B
#define SMEM_BYTES (256*WSTR*4 + 256*SSTR*4 + TP*8*4 + 64*4)

// packed fp32x2 FMA: d = a*b + d  (lane-wise IEEE fp32, bit-identical to fmaf)
#define FMA_F32X2(d, a, b) \
    asm("fma.rn.f32x2 %0, %1, %2, %3;" : "=l"(d) : "l"(a), "l"(b), "l"(d))

// ---- harmonics: reconstructed eigh basis (measured rounds 1-6) ----
__constant__ int   CJA[10] = {1, 1, 1, 2, 1, 1, 2, 2, 1, 1};
__constant__ int   CKA[10] = {1, 2, 2, 2, 3, 3, 3, 3, 4, 4};
__constant__ float CCA[10] = {-1.0f, 0.70710678f, 0.70710678f, -1.0f,
                              0.7106526f, 0.7035431f, 0.6690689f, -0.7432122f,
                              -0.70710678f, 0.70710678f};
__constant__ int   CJB[10] = {1, 2, 2, 2, 3, 3, 3, 3, 4, 4};
__constant__ int   CKB[10] = {1, 1, 1, 2, 1, 1, 2, 2, 1, 1};
__constant__ float CCB[10] = {0.0f, 0.70710678f, -0.70710678f, 0.0f,
                              -0.7035431f, 0.7106526f, -0.7432122f, -0.6690689f,
                              0.70710678f, 0.70710678f};

__global__ __launch_bounds__(128, 1)
void fractal_fused_kernel(const float* __restrict__ x,
                          const float* __restrict__ W,
                          const float* __restrict__ bias,
                          float* __restrict__ emb,
                          float* __restrict__ frac,
                          float* __restrict__ harm)
{
    extern __shared__ float sh[];
    float*    wT    = sh;
    float*    sT    = sh + 256 * WSTR;
    unsigned* masks = (unsigned*)(sT + 256 * SSTR);
    float*    bs    = (float*)(masks + TP * 8);

    const int t = threadIdx.x;            // 0..127
    const int base_patch = blockIdx.x * TP;

    // ---- harmonics folded into blocks 0..9 ----
    if (blockIdx.x < 10) {
        int h = blockIdx.x;
        const float norm = 0.11764705882352941f;   // 2/17
        const float pi17 = 0.18479956785822313f;   // pi/17
        #pragma unroll
        for (int q = 0; q < 2; ++q) {
            int m = t + q * 128;
            int a = m >> 4;
            int b = m & 15;
            float wa = norm * sinf((float)((a + 1) * CJA[h]) * pi17)
                            * sinf((float)((b + 1) * CKA[h]) * pi17);
            float wb = norm * sinf((float)((a + 1) * CJB[h]) * pi17)
                            * sinf((float)((b + 1) * CKB[h]) * pi17);
            harm[m * 10 + h] = CCA[h] * wa + CCB[h] * wb;
        }
    }

    if (t < 64) bs[t] = bias[t];

    // ---- stage W transposed (each thread covers k=t and k=t+128) ----
    #pragma unroll 4
    for (int j = 0; j < 64; ++j) {
        wT[t * WSTR + j]         = W[j * 256 + t];
        wT[(t + 128) * WSTR + j] = W[j * 256 + 128 + t];
    }

    // ---- stage pixels + occupancy masks ----
    const int r  = t >> 4;       // 0..7 within-patch row (also handles r+8)
    const int cc = t & 15;       // within-patch col
    #pragma unroll 4
    for (int j = 0; j < TP; ++j) {
        int pgI  = base_patch + j;
        int b    = pgI / PPB;
        int rem  = pgI - b * PPB;
        int tile = rem / 3;
        int c    = rem - tile * 3;
        int th   = tile >> 5;
        int tw   = tile & 31;
        size_t a0 = (((size_t)(b * 3 + c) * 512) + (size_t)(th * PS + r)) * 512
                    + (size_t)(tw * PS + cc);
        float v1 = x[a0];
        float v2 = x[a0 + 8 * 512];
        sT[t * SSTR + j]         = v1;
        sT[(t + 128) * SSTR + j] = v2;
        unsigned bal1 = __ballot_sync(0xffffffffu, v1 > 0.1f);
        unsigned bal2 = __ballot_sync(0xffffffffu, v2 > 0.1f);
        if ((t & 31) == 0) {
            int w = t >> 5;               // 0..3
            masks[j * 8 + w]     = bal1;  // rows 2w, 2w+1
            masks[j * 8 + 4 + w] = bal2;  // rows 8+2w, 8+2w+1
        }
    }
    __syncthreads();

    // ---- fractal dimension: all 128 threads, one patch each ----
    {
        unsigned m[8];
        #pragma unroll
        for (int w = 0; w < 8; ++w) m[w] = masks[t * 8 + w];

        int n1 = 0, n2 = 0, n3 = 0, n4;
        #pragma unroll
        for (int i = 0; i < 8; ++i) {
            unsigned rp = (m[i] & 0xffffu) | (m[i] >> 16);
            n1 += __popc((rp | (rp >> 1)) & 0x5555u);
        }
        #pragma unroll
        for (int i = 0; i < 4; ++i) {
            unsigned q = m[2 * i] | m[2 * i + 1];
            q = (q & 0xffffu) | (q >> 16);
            q = q | (q >> 1) | (q >> 2) | (q >> 3);
            n2 += __popc(q & 0x1111u);
        }
        #pragma unroll
        for (int i = 0; i < 2; ++i) {
            unsigned o = m[4*i] | m[4*i+1] | m[4*i+2] | m[4*i+3];
            o = (o & 0xffffu) | (o >> 16);
            o = o | (o >> 1) | (o >> 2) | (o >> 3) | (o >> 4) | (o >> 5) | (o >> 6) | (o >> 7);
            n3 += __popc(o & 0x0101u);
        }
        {
            unsigned a = 0;
            #pragma unroll
            for (int w = 0; w < 8; ++w) a |= m[w];
            n4 = (a != 0) ? 1 : 0;
        }
        float slope = 0.3f * (log2f((float)n1) - log2f((float)n4))
                    + 0.1f * (log2f((float)n2) - log2f((float)n3));
        frac[base_patch + t] = slope;
    }

    // ---- GEMM: 64e x 128p tile, micro-tile 8e x 8p per thread, f32x2 ----
    // e set: {eA..eA+3} u {eA+32..eA+35};  p set: {pA..pA+3} u {pA+64..pA+67}
    const int pe = t >> 4;        // 0..7
    const int pg = t & 15;        // 0..15
    const int eA = 4 * pe;
    const int pA = 4 * pg;

    unsigned long long Acc[8][4];
    #pragma unroll
    for (int e = 0; e < 8; ++e)
        #pragma unroll
        for (int p = 0; p < 4; ++p) Acc[e][p] = 0ull;

    const float* wbp = wT + eA;
    const float* sbp = sT + pA;

    #pragma unroll 4
    for (int k = 0; k < 256; ++k) {
        float4     wa = *(const float4*)(wbp + (size_t)k * WSTR);
        float4     wc = *(const float4*)(wbp + (size_t)k * WSTR + 32);
        ulonglong2 sa = *(const ulonglong2*)(sbp + (size_t)k * SSTR);
        ulonglong2 sc = *(const ulonglong2*)(sbp + (size_t)k * SSTR + 64);

        unsigned long long Wp[8], Sp[4];
        {
            unsigned w0 = __float_as_uint(wa.x), w1 = __float_as_uint(wa.y);
            unsigned w2 = __float_as_uint(wa.z), w3 = __float_as_uint(wa.w);
            unsigned w4 = __float_as_uint(wc.x), w5 = __float_as_uint(wc.y);
            unsigned w6 = __float_as_uint(wc.z), w7 = __float_as_uint(wc.w);
            asm("mov.b64 %0, {%1, %1};" : "=l"(Wp[0]) : "r"(w0));
            asm("mov.b64 %0, {%1, %1};" : "=l"(Wp[1]) : "r"(w1));
            asm("mov.b64 %0, {%1, %1};" : "=l"(Wp[2]) : "r"(w2));
            asm("mov.b64 %0, {%1, %1};" : "=l"(Wp[3]) : "r"(w3));
            asm("mov.b64 %0, {%1, %1};" : "=l"(Wp[4]) : "r"(w4));
            asm("mov.b64 %0, {%1, %1};" : "=l"(Wp[5]) : "r"(w5));
            asm("mov.b64 %0, {%1, %1};" : "=l"(Wp[6]) : "r"(w6));
            asm("mov.b64 %0, {%1, %1};" : "=l"(Wp[7]) : "r"(w7));
        }
        Sp[0] = sa.x; Sp[1] = sa.y; Sp[2] = sc.x; Sp[3] = sc.y;

        #pragma unroll
        for (int e = 0; e < 8; ++e)
            #pragma unroll
            for (int p = 0; p < 4; ++p)
                FMA_F32X2(Acc[e][p], Wp[e], Sp[p]);
    }

    // ---- epilogue: bias + store ----
    float bv[8];
    #pragma unroll
    for (int i = 0; i < 4; ++i) {
        bv[i]     = bs[eA + i];
        bv[4 + i] = bs[eA + 32 + i];
    }

    #pragma unroll
    for (int pj = 0; pj < 4; ++pj) {
        int p = (pj < 2) ? (pA + 2 * pj) : (pA + 64 + 2 * (pj - 2));
        float lo[8], hi[8];
        #pragma unroll
        for (int e = 0; e < 8; ++e)
            asm("mov.b64 {%0, %1}, %2;" : "=f"(lo[e]), "=f"(hi[e]) : "l"(Acc[e][pj]));

        float4 o0, o1;
        o0.x = lo[0] + bv[0]; o0.y = lo[1] + bv[1]; o0.z = lo[2] + bv[2]; o0.w = lo[3] + bv[3];
        o1.x = lo[4] + bv[4]; o1.y = lo[5] + bv[5]; o1.z = lo[6] + bv[6]; o1.w = lo[7] + bv[7];
        *(float4*)&emb[(size_t)(base_patch + p) * EMB + eA]      = o0;
        *(float4*)&emb[(size_t)(base_patch + p) * EMB + eA + 32] = o1;

        o0.x = hi[0] + bv[0]; o0.y = hi[1] + bv[1]; o0.z = hi[2] + bv[2]; o0.w = hi[3] + bv[3];
        o1.x = hi[4] + bv[4]; o1.y = hi[5] + bv[5]; o1.z = hi[6] + bv[6]; o1.w = hi[7] + bv[7];
        *(float4*)&emb[(size_t)(base_patch + p + 1) * EMB + eA]      = o0;
        *(float4*)&emb[(size_t)(base_patch + p + 1) * EMB + eA + 32] = o1;
    }
}

extern "C" void kernel_launch(void* const* d_in, const int* in_sizes, int n_in,
                              void* d_out, int out_size)
{
    const float* x    = (const float*)d_in[0];
    const float* W    = (const float*)d_in[1];
    const float* bias = (const float*)d_in[2];

    float* out  = (float*)d_out;
    float* emb  = out;
    float* frac = out + (size_t)NPATCH * EMB;
    float* harm = frac + NPATCH;

    cudaFuncSetAttribute(fractal_fused_kernel,
                         cudaFuncAttributeMaxDynamicSharedMemorySize, SMEM_BYTES);
    fractal_fused_kernel<<<NBLK, 128, SMEM_BYTES>>>(x, W, bias, emb, frac, harm);
}

// round 12
// speedup vs baseline: 1.6737x; 1.6737x over previous
#include <cuda_runtime.h>
#include <math.h>

#define PS      16
#define EMB     64
#define TP      128           // patches per block
#define WSTR    68            // wT row stride (floats), half-tile: 128 k-rows
#define SSTR    132           // sT row stride (floats), half-tile: 128 k-rows
#define NPATCH  98304
#define PPB     3072          // patches per batch image
#define NBLK    (NPATCH / TP) // 768

// dynamic shared layout (floats), per k-phase (128 k-rows):
//   wT   [128][WSTR]  : 34816 B
//   sT   [128][SSTR]  : 67584 B
//   masks[128][8] u32 : 4096 B
//   bs   [64]         : 256 B      total = 106752 B -> 2 blocks/SM
#define SMEM_BYTES (128*WSTR*4 + 128*SSTR*4 + TP*8*4 + 64*4)

// packed fp32x2 FMA: d = a*b + d  (lane-wise IEEE fp32, bit-identical to fmaf)
#define FMA_F32X2(d, a, b) \
    asm("fma.rn.f32x2 %0, %1, %2, %3;" : "=l"(d) : "l"(a), "l"(b), "l"(d))

// ---- harmonics: reconstructed eigh basis (measured rounds 1-6) ----
__constant__ int   CJA[10] = {1, 1, 1, 2, 1, 1, 2, 2, 1, 1};
__constant__ int   CKA[10] = {1, 2, 2, 2, 3, 3, 3, 3, 4, 4};
__constant__ float CCA[10] = {-1.0f, 0.70710678f, 0.70710678f, -1.0f,
                              0.7106526f, 0.7035431f, 0.6690689f, -0.7432122f,
                              -0.70710678f, 0.70710678f};
__constant__ int   CJB[10] = {1, 2, 2, 2, 3, 3, 3, 3, 4, 4};
__constant__ int   CKB[10] = {1, 1, 1, 2, 1, 1, 2, 2, 1, 1};
__constant__ float CCB[10] = {0.0f, 0.70710678f, -0.70710678f, 0.0f,
                              -0.7035431f, 0.7106526f, -0.7432122f, -0.6690689f,
                              0.70710678f, 0.70710678f};

__global__ __launch_bounds__(256, 2)
void fractal_fused_kernel(const float* __restrict__ x,
                          const float* __restrict__ W,
                          const float* __restrict__ bias,
                          float* __restrict__ emb,
                          float* __restrict__ frac,
                          float* __restrict__ harm)
{
    extern __shared__ float sh[];
    float*    wT    = sh;                       // [128][WSTR]
    float*    sT    = sh + 128 * WSTR;          // [128][SSTR]
    unsigned* masks = (unsigned*)(sT + 128 * SSTR);
    float*    bs    = (float*)(masks + TP * 8);

    const int t = threadIdx.x;            // 0..255
    const int base_patch = blockIdx.x * TP;

    // ---- harmonics folded into blocks 0..9 (one element per thread) ----
    if (blockIdx.x < 10) {
        int h = blockIdx.x;
        int a = t >> 4;
        int b = t & 15;
        const float norm = 0.11764705882352941f;   // 2/17
        const float pi17 = 0.18479956785822313f;   // pi/17
        float wa = norm * sinf((float)((a + 1) * CJA[h]) * pi17)
                        * sinf((float)((b + 1) * CKA[h]) * pi17);
        float wb = norm * sinf((float)((a + 1) * CJB[h]) * pi17)
                        * sinf((float)((b + 1) * CKB[h]) * pi17);
        harm[t * 10 + h] = CCA[h] * wa + CCB[h] * wb;
    }

    if (t < 64) bs[t] = bias[t];

    // thread -> micro-tile mapping (8e x 4p):
    //   pgi = t>>3 (0..31) -> pA = 4*pgi  (p in {pA..pA+3})
    //   pei = t&7  (0..7)  -> eA = 4*pei  (e in {eA..eA+3} u {eA+32..eA+35})
    const int pgi = t >> 3;
    const int pei = t & 7;
    const int pA  = 4 * pgi;
    const int eA  = 4 * pei;

    unsigned long long Acc[8][2];
    #pragma unroll
    for (int e = 0; e < 8; ++e) { Acc[e][0] = 0ull; Acc[e][1] = 0ull; }

    // x staging coords
    const int rr = (t >> 4) & 7;   // within-phase patch row 0..7
    const int cc = t & 15;         // patch col
    const int jh = t >> 7;         // 0/1: which of 2 patches per stage iter
    const int w  = t >> 5;         // warp id 0..7

    #pragma unroll
    for (int ph = 0; ph < 2; ++ph) {
        // ---- stage W half: wT[kk][e] = W[e][128*ph + kk] ----
        {
            const int kk = t & 127;
            const int eh = t >> 7;           // 0/1
            #pragma unroll 8
            for (int it = 0; it < 32; ++it) {
                int e = 2 * it + eh;
                wT[kk * WSTR + e] = W[e * 256 + 128 * ph + kk];
            }
        }

        // ---- stage x half (patch rows 8*ph .. 8*ph+7) + ballots ----
        {
            const int kk = rr * 16 + cc;     // phase-local k row
            #pragma unroll 4
            for (int jj = 0; jj < 64; ++jj) {
                int j    = 2 * jj + jh;
                int pgI  = base_patch + j;
                int b    = pgI / PPB;
                int rem  = pgI - b * PPB;
                int tile = rem / 3;
                int c    = rem - tile * 3;
                int th   = tile >> 5;
                int tw   = tile & 31;
                size_t a0 = (((size_t)(b * 3 + c) * 512)
                             + (size_t)(th * PS + 8 * ph + rr)) * 512
                            + (size_t)(tw * PS + cc);
                float v = x[a0];
                sT[kk * SSTR + j] = v;
                unsigned bal = __ballot_sync(0xffffffffu, v > 0.1f);
                if ((t & 31) == 0)
                    masks[j * 8 + 4 * ph + (w & 3)] = bal;
            }
        }
        __syncthreads();

        // ---- GEMM half: k = 0..127 (phase-local) ----
        const float* wbp = wT + eA;
        const float* sbp = sT + pA;
        #pragma unroll 4
        for (int k = 0; k < 128; ++k) {
            float4     wa = *(const float4*)(wbp + (size_t)k * WSTR);
            float4     wc = *(const float4*)(wbp + (size_t)k * WSTR + 32);
            ulonglong2 sv = *(const ulonglong2*)(sbp + (size_t)k * SSTR);

            unsigned long long Wp[8];
            {
                unsigned w0 = __float_as_uint(wa.x), w1 = __float_as_uint(wa.y);
                unsigned w2 = __float_as_uint(wa.z), w3 = __float_as_uint(wa.w);
                unsigned w4 = __float_as_uint(wc.x), w5 = __float_as_uint(wc.y);
                unsigned w6 = __float_as_uint(wc.z), w7 = __float_as_uint(wc.w);
                asm("mov.b64 %0, {%1, %1};" : "=l"(Wp[0]) : "r"(w0));
                asm("mov.b64 %0, {%1, %1};" : "=l"(Wp[1]) : "r"(w1));
                asm("mov.b64 %0, {%1, %1};" : "=l"(Wp[2]) : "r"(w2));
                asm("mov.b64 %0, {%1, %1};" : "=l"(Wp[3]) : "r"(w3));
                asm("mov.b64 %0, {%1, %1};" : "=l"(Wp[4]) : "r"(w4));
                asm("mov.b64 %0, {%1, %1};" : "=l"(Wp[5]) : "r"(w5));
                asm("mov.b64 %0, {%1, %1};" : "=l"(Wp[6]) : "r"(w6));
                asm("mov.b64 %0, {%1, %1};" : "=l"(Wp[7]) : "r"(w7));
            }
            #pragma unroll
            for (int e = 0; e < 8; ++e) {
                FMA_F32X2(Acc[e][0], Wp[e], sv.x);
                FMA_F32X2(Acc[e][1], Wp[e], sv.y);
            }
        }
        if (ph == 0) __syncthreads();   // protect sT/wT before restage
    }

    // ---- fractal dimension: threads 0..127, one patch each ----
    if (t < TP) {
        unsigned m[8];
        #pragma unroll
        for (int i = 0; i < 8; ++i) m[i] = masks[t * 8 + i];

        int n1 = 0, n2 = 0, n3 = 0, n4;
        #pragma unroll
        for (int i = 0; i < 8; ++i) {
            unsigned rp = (m[i] & 0xffffu) | (m[i] >> 16);
            n1 += __popc((rp | (rp >> 1)) & 0x5555u);
        }
        #pragma unroll
        for (int i = 0; i < 4; ++i) {
            unsigned q = m[2 * i] | m[2 * i + 1];
            q = (q & 0xffffu) | (q >> 16);
            q = q | (q >> 1) | (q >> 2) | (q >> 3);
            n2 += __popc(q & 0x1111u);
        }
        #pragma unroll
        for (int i = 0; i < 2; ++i) {
            unsigned o = m[4*i] | m[4*i+1] | m[4*i+2] | m[4*i+3];
            o = (o & 0xffffu) | (o >> 16);
            o = o | (o >> 1) | (o >> 2) | (o >> 3) | (o >> 4) | (o >> 5) | (o >> 6) | (o >> 7);
            n3 += __popc(o & 0x0101u);
        }
        {
            unsigned a = 0;
            #pragma unroll
            for (int i = 0; i < 8; ++i) a |= m[i];
            n4 = (a != 0) ? 1 : 0;
        }
        float slope = 0.3f * (log2f((float)n1) - log2f((float)n4))
                    + 0.1f * (log2f((float)n2) - log2f((float)n3));
        frac[base_patch + t] = slope;
    }

    // ---- epilogue: bias + store (8 x STG.128 per thread) ----
    float bv[8];
    #pragma unroll
    for (int i = 0; i < 4; ++i) {
        bv[i]     = bs[eA + i];
        bv[4 + i] = bs[eA + 32 + i];
    }

    #pragma unroll
    for (int pj = 0; pj < 4; ++pj) {
        float v[8];
        #pragma unroll
        for (int e = 0; e < 8; ++e) {
            float lo, hi;
            asm("mov.b64 {%0, %1}, %2;" : "=f"(lo), "=f"(hi) : "l"(Acc[e][pj >> 1]));
            v[e] = (pj & 1) ? hi : lo;
        }
        float4 o0, o1;
        o0.x = v[0] + bv[0]; o0.y = v[1] + bv[1]; o0.z = v[2] + bv[2]; o0.w = v[3] + bv[3];
        o1.x = v[4] + bv[4]; o1.y = v[5] + bv[5]; o1.z = v[6] + bv[6]; o1.w = v[7] + bv[7];
        size_t row = (size_t)(base_patch + pA + pj) * EMB;
        *(float4*)&emb[row + eA]      = o0;
        *(float4*)&emb[row + eA + 32] = o1;
    }
}

extern "C" void kernel_launch(void* const* d_in, const int* in_sizes, int n_in,
                              void* d_out, int out_size)
{
    const float* x    = (const float*)d_in[0];
    const float* W    = (const float*)d_in[1];
    const float* bias = (const float*)d_in[2];

    float* out  = (float*)d_out;
    float* emb  = out;
    float* frac = out + (size_t)NPATCH * EMB;
    float* harm = frac + NPATCH;

    cudaFuncSetAttribute(fractal_fused_kernel,
                         cudaFuncAttributeMaxDynamicSharedMemorySize, SMEM_BYTES);
    fractal_fused_kernel<<<NBLK, 256, SMEM_BYTES>>>(x, W, bias, emb, frac, harm);
}

// round 14
// speedup vs baseline: 1.8673x; 1.1157x over previous
#include <cuda_runtime.h>
#include <math.h>

#define PS      16
#define EMB     64
#define TP      128           // patches per block
#define WSTR    68            // wT row stride (floats)
#define SSTR    132           // sT row stride (floats)
#define KP      64            // k-rows per phase
#define NPATCH  98304
#define PPB     3072          // patches per batch image
#define NBLK    (NPATCH / TP) // 768

// dynamic shared layout (floats), per k-phase (64 k-rows):
//   wT   [64][WSTR]   : 17408 B
//   sT   [64][SSTR]   : 33792 B
//   masks[128][8] u32 : 4096 B
//   bs   [64]         : 256 B      total = 55552 B -> 3 blocks/SM
#define SMEM_BYTES (KP*WSTR*4 + KP*SSTR*4 + TP*8*4 + 64*4)

// packed fp32x2 FMA: d = a*b + d  (lane-wise IEEE fp32, bit-identical to fmaf)
#define FMA_F32X2(d, a, b) \
    asm("fma.rn.f32x2 %0, %1, %2, %3;" : "=l"(d) : "l"(a), "l"(b), "l"(d))

// ---- harmonics: reconstructed eigh basis (measured rounds 1-6) ----
__constant__ int   CJA[10] = {1, 1, 1, 2, 1, 1, 2, 2, 1, 1};
__constant__ int   CKA[10] = {1, 2, 2, 2, 3, 3, 3, 3, 4, 4};
__constant__ float CCA[10] = {-1.0f, 0.70710678f, 0.70710678f, -1.0f,
                              0.7106526f, 0.7035431f, 0.6690689f, -0.7432122f,
                              -0.70710678f, 0.70710678f};
__constant__ int   CJB[10] = {1, 2, 2, 2, 3, 3, 3, 3, 4, 4};
__constant__ int   CKB[10] = {1, 1, 1, 2, 1, 1, 2, 2, 1, 1};
__constant__ float CCB[10] = {0.0f, 0.70710678f, -0.70710678f, 0.0f,
                              -0.7035431f, 0.7106526f, -0.7432122f, -0.6690689f,
                              0.70710678f, 0.70710678f};

__global__ __launch_bounds__(256, 3)
void fractal_fused_kernel(const float* __restrict__ x,
                          const float* __restrict__ W,
                          const float* __restrict__ bias,
                          float* __restrict__ emb,
                          float* __restrict__ frac,
                          float* __restrict__ harm)
{
    extern __shared__ float sh[];
    float*    wT    = sh;                       // [KP][WSTR]
    float*    sT    = sh + KP * WSTR;           // [KP][SSTR]
    unsigned* masks = (unsigned*)(sT + KP * SSTR);
    float*    bs    = (float*)(masks + TP * 8);

    const int t = threadIdx.x;            // 0..255
    const int base_patch = blockIdx.x * TP;

    // ---- harmonics folded into blocks 0..9 (one element per thread) ----
    if (blockIdx.x < 10) {
        int h = blockIdx.x;
        int a = t >> 4;
        int b = t & 15;
        const float norm = 0.11764705882352941f;   // 2/17
        const float pi17 = 0.18479956785822313f;   // pi/17
        float wa = norm * sinf((float)((a + 1) * CJA[h]) * pi17)
                        * sinf((float)((b + 1) * CKA[h]) * pi17);
        float wb = norm * sinf((float)((a + 1) * CJB[h]) * pi17)
                        * sinf((float)((b + 1) * CKB[h]) * pi17);
        harm[t * 10 + h] = CCA[h] * wa + CCB[h] * wb;
    }

    if (t < 64) bs[t] = bias[t];

    // thread -> micro-tile (8e x 4p), e pre-paired:
    //   pgi = t>>3 -> pA = 4*pgi ; pei = t&7 -> eA = 4*pei
    //   e pairs: (eA,eA+1),(eA+2,eA+3),(eA+32,eA+33),(eA+34,eA+35)
    const int pgi = t >> 3;
    const int pei = t & 7;
    const int pA  = 4 * pgi;
    const int eA  = 4 * pei;

    unsigned long long Acc[4][4];   // [e-pair][p]
    #pragma unroll
    for (int e = 0; e < 4; ++e)
        #pragma unroll
        for (int p = 0; p < 4; ++p) Acc[e][p] = 0ull;

    // staging coords
    const int cc  = t & 15;         // patch col
    const int rr2 = (t >> 4) & 1;   // row parity within row-pair
    const int wrp = t >> 5;         // warp 0..7
    const int kkw = t & 63;         // W-stage k row
    const int ehw = t >> 6;         // W-stage e offset 0..3

    #pragma unroll
    for (int ph = 0; ph < 4; ++ph) {
        // ---- stage W quarter: wT[kk][e] = W[e][64*ph + kk] ----
        #pragma unroll 4
        for (int i = 0; i < 16; ++i) {
            int e = 4 * i + ehw;
            wT[kkw * WSTR + e] = W[e * 256 + KP * ph + kkw];
        }

        // ---- stage x quarter (patch rows 4ph..4ph+3) + ballots ----
        #pragma unroll 2
        for (int i = 0; i < 16; ++i) {
            int j    = 8 * i + wrp;
            int pgI  = base_patch + j;
            int b    = pgI / PPB;
            int rem  = pgI - b * PPB;
            int tile = rem / 3;
            int c    = rem - tile * 3;
            int th   = tile >> 5;
            int tw   = tile & 31;
            size_t abase = (((size_t)(b * 3 + c) * 512)
                            + (size_t)(th * PS + 4 * ph + rr2)) * 512
                           + (size_t)(tw * PS + cc);
            #pragma unroll
            for (int a = 0; a < 2; ++a) {
                float v = x[abase + (size_t)(2 * a) * 512];
                int kk = (2 * a + rr2) * 16 + cc;
                sT[kk * SSTR + j] = v;
                unsigned bal = __ballot_sync(0xffffffffu, v > 0.1f);
                if ((t & 31) == 0)
                    masks[j * 8 + 2 * ph + a] = bal;
            }
        }
        __syncthreads();

        // ---- GEMM quarter: k = 0..63 (phase-local) ----
        const float* wbp = wT + eA;
        const float* sbp = sT + pA;
        #pragma unroll 4
        for (int k = 0; k < KP; ++k) {
            ulonglong2 wa = *(const ulonglong2*)(wbp + (size_t)k * WSTR);      // {e0,e1}{e2,e3}
            ulonglong2 wc = *(const ulonglong2*)(wbp + (size_t)k * WSTR + 32); // {e32,e33}{e34,e35}
            float4     sv = *(const float4*)(sbp + (size_t)k * SSTR);

            unsigned long long S[4];
            {
                unsigned s0 = __float_as_uint(sv.x), s1 = __float_as_uint(sv.y);
                unsigned s2 = __float_as_uint(sv.z), s3 = __float_as_uint(sv.w);
                asm("mov.b64 %0, {%1, %1};" : "=l"(S[0]) : "r"(s0));
                asm("mov.b64 %0, {%1, %1};" : "=l"(S[1]) : "r"(s1));
                asm("mov.b64 %0, {%1, %1};" : "=l"(S[2]) : "r"(s2));
                asm("mov.b64 %0, {%1, %1};" : "=l"(S[3]) : "r"(s3));
            }
            #pragma unroll
            for (int p = 0; p < 4; ++p) {
                FMA_F32X2(Acc[0][p], wa.x, S[p]);
                FMA_F32X2(Acc[1][p], wa.y, S[p]);
                FMA_F32X2(Acc[2][p], wc.x, S[p]);
                FMA_F32X2(Acc[3][p], wc.y, S[p]);
            }
        }
        if (ph < 3) __syncthreads();   // protect tiles before restage
    }

    // ---- fractal dimension: threads 0..127, one patch each ----
    if (t < TP) {
        unsigned m[8];
        #pragma unroll
        for (int i = 0; i < 8; ++i) m[i] = masks[t * 8 + i];

        int n1 = 0, n2 = 0, n3 = 0, n4;
        #pragma unroll
        for (int i = 0; i < 8; ++i) {
            unsigned rp = (m[i] & 0xffffu) | (m[i] >> 16);
            n1 += __popc((rp | (rp >> 1)) & 0x5555u);
        }
        #pragma unroll
        for (int i = 0; i < 4; ++i) {
            unsigned q = m[2 * i] | m[2 * i + 1];
            q = (q & 0xffffu) | (q >> 16);
            q = q | (q >> 1) | (q >> 2) | (q >> 3);
            n2 += __popc(q & 0x1111u);
        }
        #pragma unroll
        for (int i = 0; i < 2; ++i) {
            unsigned o = m[4*i] | m[4*i+1] | m[4*i+2] | m[4*i+3];
            o = (o & 0xffffu) | (o >> 16);
            o = o | (o >> 1) | (o >> 2) | (o >> 3) | (o >> 4) | (o >> 5) | (o >> 6) | (o >> 7);
            n3 += __popc(o & 0x0101u);
        }
        {
            unsigned a = 0;
            #pragma unroll
            for (int i = 0; i < 8; ++i) a |= m[i];
            n4 = (a != 0) ? 1 : 0;
        }
        float slope = 0.3f * (log2f((float)n1) - log2f((float)n4))
                    + 0.1f * (log2f((float)n2) - log2f((float)n3));
        frac[base_patch + t] = slope;
    }

    // ---- epilogue: bias + store (8 x STG.128 per thread) ----
    float bv[8];
    #pragma unroll
    for (int i = 0; i < 4; ++i) {
        bv[i]     = bs[eA + i];
        bv[4 + i] = bs[eA + 32 + i];
    }

    #pragma unroll
    for (int pj = 0; pj < 4; ++pj) {
        float v[8];
        #pragma unroll
        for (int e = 0; e < 4; ++e) {
            float lo, hi;
            asm("mov.b64 {%0, %1}, %2;" : "=f"(lo), "=f"(hi) : "l"(Acc[e][pj]));
            v[2 * e]     = lo;
            v[2 * e + 1] = hi;
        }
        float4 o0, o1;
        o0.x = v[0] + bv[0]; o0.y = v[1] + bv[1]; o0.z = v[2] + bv[2]; o0.w = v[3] + bv[3];
        o1.x = v[4] + bv[4]; o1.y = v[5] + bv[5]; o1.z = v[6] + bv[6]; o1.w = v[7] + bv[7];
        size_t row = (size_t)(base_patch + pA + pj) * EMB;
        *(float4*)&emb[row + eA]      = o0;
        *(float4*)&emb[row + eA + 32] = o1;
    }
}

extern "C" void kernel_launch(void* const* d_in, const int* in_sizes, int n_in,
                              void* d_out, int out_size)
{
    const float* x    = (const float*)d_in[0];
    const float* W    = (const float*)d_in[1];
    const float* bias = (const float*)d_in[2];

    float* out  = (float*)d_out;
    float* emb  = out;
    float* frac = out + (size_t)NPATCH * EMB;
    float* harm = frac + NPATCH;

    cudaFuncSetAttribute(fractal_fused_kernel,
                         cudaFuncAttributeMaxDynamicSharedMemorySize, SMEM_BYTES);
    fractal_fused_kernel<<<NBLK, 256, SMEM_BYTES>>>(x, W, bias, emb, frac, harm);
}

// round 16
// speedup vs baseline: 1.9701x; 1.0550x over previous
#include <cuda_runtime.h>
#include <cuda_bf16.h>
#include <math.h>
#include <cstdint>

#define PS      16
#define EMB     64
#define TP      128           // patches per CTA (M)
#define NPATCH  98304
#define PPB     3072
#define NBLK    (NPATCH / TP) // 768

// ---- smem byte offsets ----
// A tiles: [128 rows][128 bf16 = 256B]  (one K-phase)
// B tiles: [64 rows][128 bf16 = 256B]
#define OFF_AH    0          // 32768
#define OFF_AL    32768      // 32768
#define OFF_BH    65536      // 16384
#define OFF_BL    81920      // 16384
#define OFF_MASK  98304      // 128*8*4 = 4096
#define OFF_BS    102400     // 256
#define OFF_PADDR 102656     // 512
#define SMEM_BYTES 103168    // -> 2 CTAs/SM

__device__ __forceinline__ uint32_t smem_u32(const void* p) {
    uint32_t a;
    asm("{ .reg .u64 t; cvta.to.shared.u64 t, %1; cvt.u32.u64 %0, t; }" : "=r"(a) : "l"(p));
    return a;
}

#define LDMX4(r, addr) \
    asm volatile("ldmatrix.sync.aligned.m8n8.x4.shared.b16 {%0,%1,%2,%3}, [%4];" \
        : "=r"((r)[0]), "=r"((r)[1]), "=r"((r)[2]), "=r"((r)[3]) : "r"(addr))

#define MMA16816(c, a, b0, b1) \
    asm volatile("mma.sync.aligned.m16n8k16.row.col.f32.bf16.bf16.f32 " \
        "{%0,%1,%2,%3}, {%4,%5,%6,%7}, {%8,%9}, {%0,%1,%2,%3};" \
        : "+f"((c)[0]), "+f"((c)[1]), "+f"((c)[2]), "+f"((c)[3]) \
        : "r"((a)[0]), "r"((a)[1]), "r"((a)[2]), "r"((a)[3]), "r"(b0), "r"(b1))

// swizzled byte offset inside a [rows][128 bf16] tile (row stride 256B)
__device__ __forceinline__ uint32_t tile_off(int row, int kk) {
    return (uint32_t)row * 256u + (uint32_t)((((kk >> 3) ^ (row & 7)) << 4))
         + (uint32_t)((kk & 7) * 2);
}

__device__ __forceinline__ unsigned spread8(unsigned v) {
    v = (v | (v << 4)) & 0x0F0Fu;
    v = (v | (v << 2)) & 0x3333u;
    v = (v | (v << 1)) & 0x5555u;
    return v;
}

// split (v0,v1) into packed bf16-hi word and bf16-lo (residual) word
__device__ __forceinline__ void split2(float v0, float v1, uint32_t& hw, uint32_t& lw) {
    __nv_bfloat16 h0 = __float2bfloat16_rn(v0);
    __nv_bfloat16 h1 = __float2bfloat16_rn(v1);
    float r0 = v0 - __bfloat162float(h0);
    float r1 = v1 - __bfloat162float(h1);
    __nv_bfloat16 l0 = __float2bfloat16_rn(r0);
    __nv_bfloat16 l1 = __float2bfloat16_rn(r1);
    hw = ((uint32_t)__bfloat16_as_ushort(h1) << 16) | __bfloat16_as_ushort(h0);
    lw = ((uint32_t)__bfloat16_as_ushort(l1) << 16) | __bfloat16_as_ushort(l0);
}

// ---- harmonics: reconstructed eigh basis (measured rounds 1-6) ----
__constant__ int   CJA[10] = {1, 1, 1, 2, 1, 1, 2, 2, 1, 1};
__constant__ int   CKA[10] = {1, 2, 2, 2, 3, 3, 3, 3, 4, 4};
__constant__ float CCA[10] = {-1.0f, 0.70710678f, 0.70710678f, -1.0f,
                              0.7106526f, 0.7035431f, 0.6690689f, -0.7432122f,
                              -0.70710678f, 0.70710678f};
__constant__ int   CJB[10] = {1, 2, 2, 2, 3, 3, 3, 3, 4, 4};
__constant__ int   CKB[10] = {1, 1, 1, 2, 1, 1, 2, 2, 1, 1};
__constant__ float CCB[10] = {0.0f, 0.70710678f, -0.70710678f, 0.0f,
                              -0.7035431f, 0.7106526f, -0.7432122f, -0.6690689f,
                              0.70710678f, 0.70710678f};

__global__ __launch_bounds__(256, 2)
void fractal_fused_kernel(const float* __restrict__ x,
                          const float* __restrict__ W,
                          const float* __restrict__ bias,
                          float* __restrict__ emb,
                          float* __restrict__ frac,
                          float* __restrict__ harm)
{
    extern __shared__ char sm[];
    const uint32_t smb = smem_u32(sm);
    unsigned* masks = (unsigned*)(sm + OFF_MASK);
    float*    bs    = (float*)(sm + OFF_BS);
    unsigned* paddr = (unsigned*)(sm + OFF_PADDR);

    const int t    = threadIdx.x;       // 0..255
    const int wid  = t >> 5;            // 0..7
    const int lane = t & 31;
    const int base_patch = blockIdx.x * TP;

    // ---- harmonics folded into blocks 0..9 ----
    if (blockIdx.x < 10) {
        int h = blockIdx.x;
        int a = t >> 4;
        int b = t & 15;
        const float norm = 0.11764705882352941f;
        const float pi17 = 0.18479956785822313f;
        float wa = norm * sinf((float)((a + 1) * CJA[h]) * pi17)
                        * sinf((float)((b + 1) * CKA[h]) * pi17);
        float wb = norm * sinf((float)((a + 1) * CJB[h]) * pi17)
                        * sinf((float)((b + 1) * CKB[h]) * pi17);
        harm[t * 10 + h] = CCA[h] * wa + CCB[h] * wb;
    }

    if (t < 64) bs[t] = bias[t];

    if (t < TP) {
        int pgI  = base_patch + t;
        int b    = pgI / PPB;
        int rem  = pgI - b * PPB;
        int tile = rem / 3;
        int c    = rem - 3 * tile;
        int th   = tile >> 5;
        int tw   = tile & 31;
        paddr[t] = ((unsigned)(b * 3 + c) * 512u + (unsigned)(th * PS)) * 512u
                 + (unsigned)(tw * PS);
    }
    __syncthreads();

    // accumulators: 8 n-tiles x 4 f32 (m16n8 fragment)
    float acc[8][4];
    #pragma unroll
    for (int n = 0; n < 8; ++n)
        #pragma unroll
        for (int i = 0; i < 4; ++i) acc[n][i] = 0.0f;

    #pragma unroll
    for (int ph = 0; ph < 2; ++ph) {
        // ---- stage W half: e rows 0..63, k = 128*ph + kk ----
        {
            int e     = t >> 2;
            int kbase = (t & 3) * 32;
            const float* wr = W + e * 256 + 128 * ph + kbase;
            #pragma unroll 4
            for (int i = 0; i < 16; ++i) {
                int kk = kbase + 2 * i;
                float2 v = *(const float2*)(wr + 2 * i);
                uint32_t hw, lw;
                split2(v.x, v.y, hw, lw);
                uint32_t o = tile_off(e, kk);
                *(uint32_t*)(sm + OFF_BH + o) = hw;
                *(uint32_t*)(sm + OFF_BL + o) = lw;
            }
        }

        // ---- stage x half (pixel rows 8ph..8ph+7) + fractal ballots ----
        {
            const int kk1 = 2 * lane;        // 0..62
            const int kk2 = 2 * lane + 64;   // 64..126
            const int r1  = kk1 >> 4, c1 = kk1 & 15;
            const int r2  = kk2 >> 4, c2 = kk2 & 15;
            #pragma unroll 2
            for (int i = 0; i < 16; ++i) {
                int j = i * 8 + wid;
                unsigned pb = paddr[j];
                float2 v1 = *(const float2*)&x[pb + (unsigned)((8 * ph + r1) * 512 + c1)];
                float2 v2 = *(const float2*)&x[pb + (unsigned)((8 * ph + r2) * 512 + c2)];
                uint32_t hw, lw;
                split2(v1.x, v1.y, hw, lw);
                uint32_t o1 = tile_off(j, kk1);
                *(uint32_t*)(sm + OFF_AH + o1) = hw;
                *(uint32_t*)(sm + OFF_AL + o1) = lw;
                split2(v2.x, v2.y, hw, lw);
                uint32_t o2 = tile_off(j, kk2);
                *(uint32_t*)(sm + OFF_AH + o2) = hw;
                *(uint32_t*)(sm + OFF_AL + o2) = lw;

                unsigned bx1 = __ballot_sync(0xffffffffu, v1.x > 0.1f);
                unsigned by1 = __ballot_sync(0xffffffffu, v1.y > 0.1f);
                unsigned bx2 = __ballot_sync(0xffffffffu, v2.x > 0.1f);
                unsigned by2 = __ballot_sync(0xffffffffu, v2.y > 0.1f);
                if (lane < 4) {
                    unsigned bx = (lane < 2) ? bx1 : bx2;
                    unsigned by = (lane < 2) ? by1 : by2;
                    int sh = (lane & 1) * 16;
                    unsigned lo = spread8((bx >> sh) & 0xFFu) | (spread8((by >> sh) & 0xFFu) << 1);
                    unsigned hi = spread8((bx >> (sh + 8)) & 0xFFu) | (spread8((by >> (sh + 8)) & 0xFFu) << 1);
                    masks[j * 8 + 4 * ph + lane] = lo | (hi << 16);
                }
            }
        }
        __syncthreads();

        // ---- mma: 8 k16-steps, 8 n-tiles, 3 terms ----
        const uint32_t abh = smb + OFF_AH + (uint32_t)(wid * 16) * 256u;
        const uint32_t abl = smb + OFF_AL + (uint32_t)(wid * 16) * 256u;
        const int arow = lane & 15;
        const int akg  = lane >> 4;            // k-half select
        const int brow = (lane & 7) | ((lane & 16) >> 1);
        const int bkg  = (lane >> 3) & 1;

        #pragma unroll
        for (int ks = 0; ks < 8; ++ks) {
            uint32_t ah[4], al[4];
            uint32_t ao = (uint32_t)arow * 256u
                        + (uint32_t)((((2 * ks + akg) ^ (arow & 7)) << 4));
            LDMX4(ah, abh + ao);
            LDMX4(al, abl + ao);
            #pragma unroll
            for (int ntp = 0; ntp < 4; ++ntp) {
                int nr = ntp * 16 + brow;
                uint32_t bo = (uint32_t)nr * 256u
                            + (uint32_t)((((2 * ks + bkg) ^ (nr & 7)) << 4));
                uint32_t bh[4], bl[4];
                LDMX4(bh, smb + OFF_BH + bo);
                LDMX4(bl, smb + OFF_BL + bo);
                MMA16816(acc[2 * ntp],     ah, bh[0], bh[1]);
                MMA16816(acc[2 * ntp],     ah, bl[0], bl[1]);
                MMA16816(acc[2 * ntp],     al, bh[0], bh[1]);
                MMA16816(acc[2 * ntp + 1], ah, bh[2], bh[3]);
                MMA16816(acc[2 * ntp + 1], ah, bl[2], bl[3]);
                MMA16816(acc[2 * ntp + 1], al, bh[2], bh[3]);
            }
        }
        if (ph == 0) __syncthreads();
    }

    // ---- fractal dimension: threads 0..127, one patch each ----
    if (t < TP) {
        unsigned m[8];
        #pragma unroll
        for (int i = 0; i < 8; ++i) m[i] = masks[t * 8 + i];
        int n1 = 0, n2 = 0, n3 = 0, n4;
        #pragma unroll
        for (int i = 0; i < 8; ++i) {
            unsigned rp = (m[i] & 0xffffu) | (m[i] >> 16);
            n1 += __popc((rp | (rp >> 1)) & 0x5555u);
        }
        #pragma unroll
        for (int i = 0; i < 4; ++i) {
            unsigned q = m[2 * i] | m[2 * i + 1];
            q = (q & 0xffffu) | (q >> 16);
            q = q | (q >> 1) | (q >> 2) | (q >> 3);
            n2 += __popc(q & 0x1111u);
        }
        #pragma unroll
        for (int i = 0; i < 2; ++i) {
            unsigned o = m[4*i] | m[4*i+1] | m[4*i+2] | m[4*i+3];
            o = (o & 0xffffu) | (o >> 16);
            o = o | (o >> 1) | (o >> 2) | (o >> 3) | (o >> 4) | (o >> 5) | (o >> 6) | (o >> 7);
            n3 += __popc(o & 0x0101u);
        }
        {
            unsigned a = 0;
            #pragma unroll
            for (int i = 0; i < 8; ++i) a |= m[i];
            n4 = (a != 0) ? 1 : 0;
        }
        float slope = 0.3f * (log2f((float)n1) - log2f((float)n4))
                    + 0.1f * (log2f((float)n2) - log2f((float)n3));
        frac[base_patch + t] = slope;
    }

    // ---- epilogue: bias + store ----
    {
        const int g  = lane >> 2;       // 0..7
        const int tg = lane & 3;
        const int row0 = wid * 16 + g;
        float* e0 = emb + (size_t)(base_patch + row0) * EMB;
        float* e1 = emb + (size_t)(base_patch + row0 + 8) * EMB;
        #pragma unroll
        for (int nt = 0; nt < 8; ++nt) {
            int col = nt * 8 + 2 * tg;
            float b0 = bs[col], b1 = bs[col + 1];
            float2 o0 = make_float2(acc[nt][0] + b0, acc[nt][1] + b1);
            float2 o1 = make_float2(acc[nt][2] + b0, acc[nt][3] + b1);
            *(float2*)(e0 + col) = o0;
            *(float2*)(e1 + col) = o1;
        }
    }
}

extern "C" void kernel_launch(void* const* d_in, const int* in_sizes, int n_in,
                              void* d_out, int out_size)
{
    const float* x    = (const float*)d_in[0];
    const float* W    = (const float*)d_in[1];
    const float* bias = (const float*)d_in[2];

    float* out  = (float*)d_out;
    float* emb  = out;
    float* frac = out + (size_t)NPATCH * EMB;
    float* harm = frac + NPATCH;

    cudaFuncSetAttribute(fractal_fused_kernel,
                         cudaFuncAttributeMaxDynamicSharedMemorySize, SMEM_BYTES);
    fractal_fused_kernel<<<NBLK, 256, SMEM_BYTES>>>(x, W, bias, emb, frac, harm);
}